// round 4
// baseline (speedup 1.0000x reference)
#include <cuda_runtime.h>
#include <math.h>

// ---------------------------------------------------------------------------
// SwinV2 window attention, fp32 with packed f32x2 FMA (sm_103a).
// Pipeline: cpb_bias -> qkv_gemm (+window partition) -> attention -> proj_gemm
// ---------------------------------------------------------------------------

#define NTOK   262144           // 16 * 128 * 128 tokens
#define NWIN   4096             // 16 * 256 windows
#define HEADS  4
#define HD     32
#define DIM    128
#define QKVC   384
#define LOG100 4.605170185988091f

// Scratch (device globals: allocation-free per harness rules)
__device__ float g_qkv[(size_t)NWIN * 64 * QKVC];   // [win][n][384] q|k|v
__device__ float g_att[(size_t)NTOK * DIM];         // spatial layout [b,y,x][c]
__device__ float g_bias[HEADS * 64 * 64];           // relative position bias

typedef unsigned long long u64;

__device__ __forceinline__ u64 pack2(float lo, float hi) {
    u64 r; asm("mov.b64 %0, {%1,%2};" : "=l"(r) : "f"(lo), "f"(hi)); return r;
}
__device__ __forceinline__ void unpack2(u64 v, float& lo, float& hi) {
    asm("mov.b64 {%0,%1}, %2;" : "=f"(lo), "=f"(hi) : "l"(v));
}
__device__ __forceinline__ u64 ffma2(u64 a, u64 b, u64 c) {
    u64 d; asm("fma.rn.f32x2 %0, %1, %2, %3;" : "=l"(d) : "l"(a), "l"(b), "l"(c));
    return d;
}

// ---------------------------------------------------------------------------
// Kernel 0: continuous position bias (tiny MLP over 15x15 rel-coord table)
// ---------------------------------------------------------------------------
__global__ void cpb_bias_kernel(const float* __restrict__ w1,
                                const float* __restrict__ b1,
                                const float* __restrict__ w2)
{
    __shared__ float tab[225 * 4];
    int t = threadIdx.x;
    if (t < 225) {
        int i = t / 15, j = t % 15;
        float v0 = (float)(i - 7) * (8.0f / 7.0f);
        float v1 = (float)(j - 7) * (8.0f / 7.0f);
        // sign(v) * log2(|v|+1) / log2(8)
        float t0 = copysignf(log2f(fabsf(v0) + 1.0f) * (1.0f / 3.0f), v0);
        float t1 = copysignf(log2f(fabsf(v1) + 1.0f) * (1.0f / 3.0f), v1);
        float a0 = 0.f, a1 = 0.f, a2 = 0.f, a3 = 0.f;
        for (int jj = 0; jj < 512; ++jj) {
            float hsum = fmaxf(t0 * w1[jj] + t1 * w1[512 + jj] + b1[jj], 0.0f);
            a0 += hsum * w2[jj * 4 + 0];
            a1 += hsum * w2[jj * 4 + 1];
            a2 += hsum * w2[jj * 4 + 2];
            a3 += hsum * w2[jj * 4 + 3];
        }
        tab[t * 4 + 0] = a0; tab[t * 4 + 1] = a1;
        tab[t * 4 + 2] = a2; tab[t * 4 + 3] = a3;
    }
    __syncthreads();
    for (int p = t; p < HEADS * 64 * 64; p += blockDim.x) {
        int h = p >> 12, q = (p >> 6) & 63, k = p & 63;
        int r0 = (q >> 3) - (k >> 3);
        int r1 = (q & 7) - (k & 7);
        int idx = (r0 + 7) * 15 + (r1 + 7);
        float bt = tab[idx * 4 + h];
        g_bias[p] = 16.0f / (1.0f + expf(-bt));
    }
}

// ---------------------------------------------------------------------------
// Kernel 1: QKV GEMM  [262144,128] @ [128,384] + bias, scatter to window layout
// BM=128, BN=64, BK=64, 256 threads, f32x2 FMA (thread tile 8x4)
// ---------------------------------------------------------------------------
__global__ void __launch_bounds__(256) qkv_gemm_kernel(
    const float* __restrict__ X, const float* __restrict__ W,
    const float* __restrict__ qb, const float* __restrict__ vb)
{
    __shared__ __align__(16) float As[128 * 64];
    __shared__ __align__(16) float Bs[64 * 64];
    int tid = threadIdx.x;
    int tx = tid & 15, ty = tid >> 4;
    int rm0 = blockIdx.x * 128;
    int cn0 = blockIdx.y * 64;

    u64 acc[4][4];
#pragma unroll
    for (int p = 0; p < 4; ++p)
#pragma unroll
        for (int j = 0; j < 4; ++j) acc[p][j] = 0ull;

    for (int kc = 0; kc < 128; kc += 64) {
#pragma unroll
        for (int l = 0; l < 8; ++l) {
            int i = tid + l * 256;
            int mm = i >> 4, k4 = (i & 15) << 2;
            *(float4*)&As[mm * 64 + k4] =
                *(const float4*)&X[(size_t)(rm0 + mm) * 128 + kc + k4];
        }
#pragma unroll
        for (int l = 0; l < 4; ++l) {
            int i = tid + l * 256;
            int kk = i >> 4, n4 = (i & 15) << 2;
            *(float4*)&Bs[kk * 64 + n4] =
                *(const float4*)&W[(size_t)(kc + kk) * QKVC + cn0 + n4];
        }
        __syncthreads();
#pragma unroll 8
        for (int k = 0; k < 64; ++k) {
            float4 b4 = *(const float4*)&Bs[k * 64 + tx * 4];
            u64 bb[4] = { pack2(b4.x, b4.x), pack2(b4.y, b4.y),
                          pack2(b4.z, b4.z), pack2(b4.w, b4.w) };
            float a[8];
#pragma unroll
            for (int i2 = 0; i2 < 8; ++i2) a[i2] = As[(ty * 8 + i2) * 64 + k];
#pragma unroll
            for (int p = 0; p < 4; ++p) {
                u64 a2 = pack2(a[2 * p], a[2 * p + 1]);
#pragma unroll
                for (int j = 0; j < 4; ++j) acc[p][j] = ffma2(a2, bb[j], acc[p][j]);
            }
        }
        __syncthreads();
    }

    int c0 = cn0 + tx * 4;
    float bias[4];
#pragma unroll
    for (int j = 0; j < 4; ++j) {
        int c = c0 + j;
        bias[j] = (c < 128) ? qb[c] : ((c < 256) ? 0.0f : vb[c - 256]);
    }
#pragma unroll
    for (int p = 0; p < 4; ++p) {
        float lo[4], hi[4];
#pragma unroll
        for (int j = 0; j < 4; ++j) unpack2(acc[p][j], lo[j], hi[j]);
#pragma unroll
        for (int r = 0; r < 2; ++r) {
            int gr = rm0 + ty * 8 + 2 * p + r;
            int b  = gr >> 14;
            int rem = gr & 16383;
            int y = rem >> 7, xx = rem & 127;
            int wi = ((y >> 3) << 4) + (xx >> 3);
            int n  = ((y & 7) << 3) + (xx & 7);
            int qrow = ((b << 8) + wi) * 64 + n;
            float4 v;
            if (r == 0) v = make_float4(lo[0] + bias[0], lo[1] + bias[1],
                                        lo[2] + bias[2], lo[3] + bias[3]);
            else        v = make_float4(hi[0] + bias[0], hi[1] + bias[1],
                                        hi[2] + bias[2], hi[3] + bias[3]);
            *(float4*)&g_qkv[(size_t)qrow * QKVC + c0] = v;
        }
    }
}

// ---------------------------------------------------------------------------
// Kernel 2: per-(window, head) cosine attention. 64 threads = 64 query rows.
// cos-sim factored as dot(q_raw,k_raw) * (1/|q|) * (1/|k|) * scale
// ---------------------------------------------------------------------------
__global__ void __launch_bounds__(64) attn_kernel(
    const float* __restrict__ mask, const float* __restrict__ logit_scale)
{
    __shared__ __align__(16) float ks[64 * 32];
    __shared__ __align__(16) float vs[64 * 32];
    __shared__ float rk[64];
    __shared__ float bm[64 * 65];   // bias + mask, padded stride 65

    int t = threadIdx.x;
    int lane = t & 31, wid = t >> 5;
    int win = blockIdx.x;
    int h   = blockIdx.y;
    int wi  = win & 255;

    const float* base = &g_qkv[(size_t)win * 64 * QKVC];

    // V tile (coalesced)
    for (int idx = t; idx < 2048; idx += 64) {
        int n = idx >> 5, d = idx & 31;
        vs[idx] = base[n * QKVC + 256 + h * 32 + d];
    }
    // K tile + per-row inverse norms (warp reduce during load)
    for (int it = 0; it < 32; ++it) {
        int n = it * 2 + wid;
        float val = base[n * QKVC + 128 + h * 32 + lane];
        ks[n * 32 + lane] = val;
        float ssq = val * val;
#pragma unroll
        for (int off = 16; off > 0; off >>= 1)
            ssq += __shfl_xor_sync(0xffffffffu, ssq, off);
        if (lane == 0) rk[n] = 1.0f / fmaxf(sqrtf(ssq), 1e-12f);
    }
    // bias + shifted-window mask
    {
        const float* gb = &g_bias[h * 4096];
        const float* gm = &mask[(size_t)wi * 4096];
        for (int idx = t; idx < 4096; idx += 64) {
            int q = idx >> 6, k = idx & 63;
            bm[q * 65 + k] = gb[idx] + gm[idx];
        }
    }
    // own query row into registers
    float4 q4[8];
    const float* qp = &base[t * QKVC + h * 32];
    float ssqq = 0.0f;
#pragma unroll
    for (int i = 0; i < 8; ++i) {
        q4[i] = *(const float4*)(qp + 4 * i);
        ssqq += q4[i].x * q4[i].x + q4[i].y * q4[i].y
              + q4[i].z * q4[i].z + q4[i].w * q4[i].w;
    }
    float rq = 1.0f / fmaxf(sqrtf(ssqq), 1e-12f);
    float s  = expf(fminf(logit_scale[h], LOG100));
    float rqs = rq * s;

    u64 q2[16];
#pragma unroll
    for (int i = 0; i < 8; ++i) {
        q2[2 * i]     = pack2(q4[i].x, q4[i].y);
        q2[2 * i + 1] = pack2(q4[i].z, q4[i].w);
    }

    __syncthreads();

    // S = q . k  (fully unrolled so att[] stays in registers)
    float att[64];
    const float* bmr = &bm[t * 65];
#pragma unroll
    for (int kk = 0; kk < 64; ++kk) {
        const u64* krow = (const u64*)&ks[kk * 32];
        u64 acc = 0ull;
#pragma unroll
        for (int p = 0; p < 16; ++p) acc = ffma2(q2[p], krow[p], acc);
        float lo, hi; unpack2(acc, lo, hi);
        att[kk] = (lo + hi) * (rqs * rk[kk]) + bmr[kk];
    }

    // softmax over kk (per-thread row)
    float m = att[0];
#pragma unroll
    for (int kk = 1; kk < 64; ++kk) m = fmaxf(m, att[kk]);
    float sum = 0.0f;
#pragma unroll
    for (int kk = 0; kk < 64; ++kk) { att[kk] = __expf(att[kk] - m); sum += att[kk]; }
    float rs = 1.0f / sum;

    // out = P @ V
    u64 o2[16];
#pragma unroll
    for (int p = 0; p < 16; ++p) o2[p] = 0ull;
#pragma unroll
    for (int kk = 0; kk < 64; ++kk) {
        u64 pp = pack2(att[kk], att[kk]);
        const u64* vrow = (const u64*)&vs[kk * 32];
#pragma unroll
        for (int p = 0; p < 16; ++p) o2[p] = ffma2(pp, vrow[p], o2[p]);
    }

    // fused window reverse: write spatial layout for the proj GEMM
    int b = win >> 8;
    int y = ((wi >> 4) << 3) + (t >> 3);
    int x = ((wi & 15) << 3) + (t & 7);
    float* dst = &g_att[(size_t)(((b << 7) + y) * 128 + x) * DIM + h * 32];
#pragma unroll
    for (int i = 0; i < 8; ++i) {
        float lo0, hi0, lo1, hi1;
        unpack2(o2[2 * i],     lo0, hi0);
        unpack2(o2[2 * i + 1], lo1, hi1);
        *(float4*)(dst + 4 * i) = make_float4(lo0 * rs, hi0 * rs, lo1 * rs, hi1 * rs);
    }
}

// ---------------------------------------------------------------------------
// Kernel 3: output projection [262144,128] @ [128,128] + bias -> d_out
// ---------------------------------------------------------------------------
__global__ void __launch_bounds__(256) proj_gemm_kernel(
    const float* __restrict__ W, const float* __restrict__ pb,
    float* __restrict__ out)
{
    __shared__ __align__(16) float As[128 * 64];
    __shared__ __align__(16) float Bs[64 * 64];
    int tid = threadIdx.x;
    int tx = tid & 15, ty = tid >> 4;
    int rm0 = blockIdx.x * 128;
    int cn0 = blockIdx.y * 64;

    u64 acc[4][4];
#pragma unroll
    for (int p = 0; p < 4; ++p)
#pragma unroll
        for (int j = 0; j < 4; ++j) acc[p][j] = 0ull;

    for (int kc = 0; kc < 128; kc += 64) {
#pragma unroll
        for (int l = 0; l < 8; ++l) {
            int i = tid + l * 256;
            int mm = i >> 4, k4 = (i & 15) << 2;
            *(float4*)&As[mm * 64 + k4] =
                *(const float4*)&g_att[(size_t)(rm0 + mm) * DIM + kc + k4];
        }
#pragma unroll
        for (int l = 0; l < 4; ++l) {
            int i = tid + l * 256;
            int kk = i >> 4, n4 = (i & 15) << 2;
            *(float4*)&Bs[kk * 64 + n4] =
                *(const float4*)&W[(size_t)(kc + kk) * DIM + cn0 + n4];
        }
        __syncthreads();
#pragma unroll 8
        for (int k = 0; k < 64; ++k) {
            float4 b4 = *(const float4*)&Bs[k * 64 + tx * 4];
            u64 bb[4] = { pack2(b4.x, b4.x), pack2(b4.y, b4.y),
                          pack2(b4.z, b4.z), pack2(b4.w, b4.w) };
            float a[8];
#pragma unroll
            for (int i2 = 0; i2 < 8; ++i2) a[i2] = As[(ty * 8 + i2) * 64 + k];
#pragma unroll
            for (int p = 0; p < 4; ++p) {
                u64 a2 = pack2(a[2 * p], a[2 * p + 1]);
#pragma unroll
                for (int j = 0; j < 4; ++j) acc[p][j] = ffma2(a2, bb[j], acc[p][j]);
            }
        }
        __syncthreads();
    }

    int c0 = cn0 + tx * 4;
    float bias[4];
#pragma unroll
    for (int j = 0; j < 4; ++j) bias[j] = pb[c0 + j];
#pragma unroll
    for (int p = 0; p < 4; ++p) {
        float lo[4], hi[4];
#pragma unroll
        for (int j = 0; j < 4; ++j) unpack2(acc[p][j], lo[j], hi[j]);
#pragma unroll
        for (int r = 0; r < 2; ++r) {
            int gr = rm0 + ty * 8 + 2 * p + r;
            float4 v;
            if (r == 0) v = make_float4(lo[0] + bias[0], lo[1] + bias[1],
                                        lo[2] + bias[2], lo[3] + bias[3]);
            else        v = make_float4(hi[0] + bias[0], hi[1] + bias[1],
                                        hi[2] + bias[2], hi[3] + bias[3]);
            *(float4*)&out[(size_t)gr * DIM + c0] = v;
        }
    }
}

// ---------------------------------------------------------------------------
extern "C" void kernel_launch(void* const* d_in, const int* in_sizes, int n_in,
                              void* d_out, int out_size)
{
    const float* x           = (const float*)d_in[0];
    const float* mask        = (const float*)d_in[1];
    const float* qkv_w       = (const float*)d_in[2];
    const float* q_bias      = (const float*)d_in[3];
    const float* v_bias      = (const float*)d_in[4];
    const float* logit_scale = (const float*)d_in[5];
    const float* cpb_w1      = (const float*)d_in[6];
    const float* cpb_b1      = (const float*)d_in[7];
    const float* cpb_w2      = (const float*)d_in[8];
    const float* proj_w      = (const float*)d_in[9];
    const float* proj_b      = (const float*)d_in[10];
    float* out = (float*)d_out;

    cpb_bias_kernel<<<1, 256>>>(cpb_w1, cpb_b1, cpb_w2);
    qkv_gemm_kernel<<<dim3(2048, 6), 256>>>(x, qkv_w, q_bias, v_bias);
    attn_kernel<<<dim3(4096, 4), 64>>>(mask, logit_scale);
    proj_gemm_kernel<<<dim3(2048, 2), 256>>>(proj_w, proj_b, out);
}